// round 10
// baseline (speedup 1.0000x reference)
#include <cuda_runtime.h>
#include <cuda_fp16.h>
#include <cstdint>

#define MAX_NODES 100000
#define MAX_EDGES 1600000
#define HID 64
#define N_GRAPHS 64

// Scratch (no cudaMalloc allowed)
__device__ __half g_h16[MAX_NODES * HID];     // 12.8 MB
__device__ float  g_agg[MAX_NODES * HID];     // 25.6 MB
__device__ float  g_dinv[MAX_NODES];
__device__ int    g_cnt[MAX_NODES];
__device__ int    g_off[MAX_NODES + 1];
__device__ int    g_cur[MAX_NODES];
__device__ int    g_bsum[512];
__device__ int    g_bbase[512];
__device__ float2 g_csr[MAX_EDGES];           // {src_as_int_bits, coef}
__device__ float  g_pooled[N_GRAPHS * HID];
__device__ float  g_cntf[N_GRAPHS];

// ---------------------------------------------------------------------------
// CSR build
// ---------------------------------------------------------------------------
__global__ void k_count(const int* __restrict__ ei, int E, int* cnt) {
    int e = blockIdx.x * blockDim.x + threadIdx.x;
    if (e < E) atomicAdd(cnt + ei[E + e], 1);
}

__global__ void k_scan_local(const int* __restrict__ cnt, int n,
                             int* __restrict__ off, int* __restrict__ bsum) {
    __shared__ int s[256];
    int i = blockIdx.x * 256 + threadIdx.x;
    int v = (i < n) ? cnt[i] : 0;
    s[threadIdx.x] = v;
    __syncthreads();
    int val = v;
#pragma unroll
    for (int d = 1; d < 256; d <<= 1) {
        int t = (threadIdx.x >= d) ? s[threadIdx.x - d] : 0;
        __syncthreads();
        val += t;
        s[threadIdx.x] = val;
        __syncthreads();
    }
    if (i < n) off[i] = val - v;
    if (threadIdx.x == 255) bsum[blockIdx.x] = val;
}

__global__ void k_scan_block(int* __restrict__ bsum, int nb, int* __restrict__ bbase) {
    __shared__ int s[512];
    int t = threadIdx.x;
    int v = (t < nb) ? bsum[t] : 0;
    s[t] = v;
    __syncthreads();
    int val = v;
#pragma unroll
    for (int d = 1; d < 512; d <<= 1) {
        int x = (t >= d) ? s[t - d] : 0;
        __syncthreads();
        val += x;
        s[t] = val;
        __syncthreads();
    }
    if (t < nb) bbase[t] = val - v;
}

__global__ void k_scan_add(const int* __restrict__ cnt, int n,
                           int* __restrict__ off, const int* __restrict__ bbase,
                           int* __restrict__ cur, float* __restrict__ dinv) {
    int i = blockIdx.x * blockDim.x + threadIdx.x;
    if (i >= n) return;
    int o = off[i] + bbase[i >> 8];
    off[i] = o;
    cur[i] = o;
    dinv[i] = rsqrtf(1.0f + (float)cnt[i]);
    if (i == n - 1) off[n] = o + cnt[i];
}

__global__ void k_fill(const int* __restrict__ ei, int E,
                       const float* __restrict__ dinv,
                       int* __restrict__ cur, float2* __restrict__ csr) {
    int e = blockIdx.x * blockDim.x + threadIdx.x;
    if (e >= E) return;
    int r = ei[e];
    int c = ei[E + e];
    float coef = dinv[r] * dinv[c];
    int pos = atomicAdd(cur + c, 1);
    csr[pos] = make_float2(__int_as_float(r), coef);
}

// ---------------------------------------------------------------------------
// TF32 tensor-core GEMM: H16[n,64] = fp16( act(A[n,K]) @ W[K,64] )
// Block: 256 thr (8 warps), tile M=128 N=64, K-chunks of 32.
// Warp w computes rows [w*16, w*16+16) x all 64 cols via mma.m16n8k8.tf32.
// ---------------------------------------------------------------------------
__device__ __forceinline__ uint32_t f2tf32(float f) {
    uint32_t r;
    asm("cvt.rna.tf32.f32 %0, %1;" : "=r"(r) : "f"(f));
    return r;
}

template <int K, bool RELU>
__global__ void __launch_bounds__(256)
k_gemm(const float* __restrict__ A, const float* __restrict__ W,
       __half* __restrict__ H, int n) {
    __shared__ uint32_t As[128][36];   // bank = 4*gr + gc  (unique over warp)
    __shared__ uint32_t Ws[32][72];    // bank = 8*gc + gr  (unique over warp)

    const int t = threadIdx.x;
    const int warpId = t >> 5;
    const int lane = t & 31;
    const int gr = lane >> 2;          // 0..7
    const int gc = lane & 3;           // 0..3
    const int warpRow = warpId * 16;
    const int rowBase = blockIdx.x * 128;

    float acc[8][4];
#pragma unroll
    for (int j = 0; j < 8; j++)
#pragma unroll
        for (int i = 0; i < 4; i++) acc[j][i] = 0.0f;

#pragma unroll
    for (int kc = 0; kc < K; kc += 32) {
        // stage A chunk: 128 rows x 32 k  (4096 elems, 16/thread as 4 float4)
#pragma unroll
        for (int it = 0; it < 4; it++) {
            int idx = (it * 256 + t) * 4;
            int r = idx >> 5;
            int c = idx & 31;
            int grow = rowBase + r;
            float4 v = make_float4(0.f, 0.f, 0.f, 0.f);
            if (grow < n) {
                v = *reinterpret_cast<const float4*>(A + (long long)grow * K + kc + c);
                if (RELU) {
                    v.x = fmaxf(v.x, 0.f); v.y = fmaxf(v.y, 0.f);
                    v.z = fmaxf(v.z, 0.f); v.w = fmaxf(v.w, 0.f);
                }
            }
            As[r][c + 0] = f2tf32(v.x);
            As[r][c + 1] = f2tf32(v.y);
            As[r][c + 2] = f2tf32(v.z);
            As[r][c + 3] = f2tf32(v.w);
        }
        // stage W chunk: 32 k x 64 cols  (2048 elems, 8/thread as 2 float4)
#pragma unroll
        for (int it = 0; it < 2; it++) {
            int idx = (it * 256 + t) * 4;
            int k = idx >> 6;
            int c = idx & 63;
            float4 v = *reinterpret_cast<const float4*>(W + (long long)(kc + k) * 64 + c);
            Ws[k][c + 0] = f2tf32(v.x);
            Ws[k][c + 1] = f2tf32(v.y);
            Ws[k][c + 2] = f2tf32(v.z);
            Ws[k][c + 3] = f2tf32(v.w);
        }
        __syncthreads();

#pragma unroll
        for (int ks = 0; ks < 4; ks++) {
            int k0 = ks * 8;
            uint32_t a0 = As[warpRow + gr    ][k0 + gc];
            uint32_t a1 = As[warpRow + gr + 8][k0 + gc];
            uint32_t a2 = As[warpRow + gr    ][k0 + gc + 4];
            uint32_t a3 = As[warpRow + gr + 8][k0 + gc + 4];
#pragma unroll
            for (int j = 0; j < 8; j++) {
                uint32_t b0 = Ws[k0 + gc    ][j * 8 + gr];
                uint32_t b1 = Ws[k0 + gc + 4][j * 8 + gr];
                asm volatile(
                    "mma.sync.aligned.m16n8k8.row.col.f32.tf32.tf32.f32 "
                    "{%0,%1,%2,%3}, {%4,%5,%6,%7}, {%8,%9}, {%0,%1,%2,%3};"
                    : "+f"(acc[j][0]), "+f"(acc[j][1]), "+f"(acc[j][2]), "+f"(acc[j][3])
                    : "r"(a0), "r"(a1), "r"(a2), "r"(a3), "r"(b0), "r"(b1));
            }
        }
        __syncthreads();
    }

    // epilogue: fp16 store. c0,c1 are adjacent cols -> one __half2 per pair.
    int row0 = rowBase + warpRow + gr;
    int row1 = row0 + 8;
#pragma unroll
    for (int j = 0; j < 8; j++) {
        int col = j * 8 + gc * 2;
        if (row0 < n) {
            __half2 p = __floats2half2_rn(acc[j][0], acc[j][1]);
            *reinterpret_cast<__half2*>(H + (long long)row0 * 64 + col) = p;
        }
        if (row1 < n) {
            __half2 p = __floats2half2_rn(acc[j][2], acc[j][3]);
            *reinterpret_cast<__half2*>(H + (long long)row1 * 64 + col) = p;
        }
    }
}

// ---------------------------------------------------------------------------
// CSR gather (fp16 h): agg[node] = sum h16[src]*coef + h16[node]*dinv^2 + b
// ---------------------------------------------------------------------------
__device__ __forceinline__ void acc_h16(float4& acc, const __half* __restrict__ h,
                                        int r, int c4, float coef) {
    uint2 u = *reinterpret_cast<const uint2*>(h + (long long)r * 64 + c4 * 4);
    __half2 a = *reinterpret_cast<__half2*>(&u.x);
    __half2 b = *reinterpret_cast<__half2*>(&u.y);
    float2 f0 = __half22float2(a);
    float2 f1 = __half22float2(b);
    acc.x += f0.x * coef; acc.y += f0.y * coef;
    acc.z += f1.x * coef; acc.w += f1.y * coef;
}

__global__ void k_gather(const int* __restrict__ off, const float2* __restrict__ csr,
                         const float* __restrict__ dinv, const __half* __restrict__ h,
                         const float* __restrict__ b, float* __restrict__ agg, int n) {
    int gid = blockIdx.x * blockDim.x + threadIdx.x;
    int node = gid >> 4;
    int c4   = gid & 15;
    if (node >= n) return;

    float di = dinv[node];
    float4 bv = reinterpret_cast<const float4*>(b)[c4];
    float4 acc = bv;
    acc_h16(acc, h, node, c4, di * di);

    int k   = off[node];
    int end = off[node + 1];

    for (; k + 2 <= end; k += 2) {
        float2 d0 = csr[k];
        float2 d1 = csr[k + 1];
        int r0 = __float_as_int(d0.x);
        int r1 = __float_as_int(d1.x);
        uint2 u0 = *reinterpret_cast<const uint2*>(h + (long long)r0 * 64 + c4 * 4);
        uint2 u1 = *reinterpret_cast<const uint2*>(h + (long long)r1 * 64 + c4 * 4);
        __half2 a0 = *reinterpret_cast<__half2*>(&u0.x);
        __half2 b0 = *reinterpret_cast<__half2*>(&u0.y);
        __half2 a1 = *reinterpret_cast<__half2*>(&u1.x);
        __half2 b1 = *reinterpret_cast<__half2*>(&u1.y);
        float2 f00 = __half22float2(a0), f01 = __half22float2(b0);
        float2 f10 = __half22float2(a1), f11 = __half22float2(b1);
        acc.x += f00.x * d0.y; acc.y += f00.y * d0.y;
        acc.z += f01.x * d0.y; acc.w += f01.y * d0.y;
        acc.x += f10.x * d1.y; acc.y += f10.y * d1.y;
        acc.z += f11.x * d1.y; acc.w += f11.y * d1.y;
    }
    if (k < end) {
        float2 d = csr[k];
        acc_h16(acc, h, __float_as_int(d.x), c4, d.y);
    }
    reinterpret_cast<float4*>(agg)[node * 16 + c4] = acc;
}

// ---------------------------------------------------------------------------
// pooling + head
// ---------------------------------------------------------------------------
#define POOL_NODES 512
__global__ void k_pool(const float* __restrict__ agg, const int* __restrict__ batch,
                       int n, float* __restrict__ pooled, float* __restrict__ cntf) {
    __shared__ float acc[N_GRAPHS * HID];
    __shared__ float cs[N_GRAPHS];
    for (int i = threadIdx.x; i < N_GRAPHS * HID; i += blockDim.x) acc[i] = 0.f;
    if (threadIdx.x < N_GRAPHS) cs[threadIdx.x] = 0.f;
    __syncthreads();

    int base = blockIdx.x * POOL_NODES;
    int ch  = threadIdx.x & 63;
    int sub = threadIdx.x >> 6;
    for (int i = sub; i < POOL_NODES; i += 4) {
        int node = base + i;
        if (node >= n) break;
        int g = batch[node];
        float v = agg[(long long)node * 64 + ch];
        atomicAdd(&acc[g * 64 + ch], v);
        if (ch == 0) atomicAdd(&cs[g], 1.0f);
    }
    __syncthreads();

    for (int i = threadIdx.x; i < N_GRAPHS * HID; i += blockDim.x) {
        float v = acc[i];
        if (v != 0.f) atomicAdd(&pooled[i], v);
    }
    if (threadIdx.x < N_GRAPHS) {
        float v = cs[threadIdx.x];
        if (v != 0.f) atomicAdd(&cntf[threadIdx.x], v);
    }
}

__global__ void k_final(const float* __restrict__ pooled, const float* __restrict__ cntf,
                        const float* __restrict__ Wlin, const float* __restrict__ blin,
                        float* __restrict__ out) {
    int t = threadIdx.x;
    int g = t >> 1;
    int o = t & 1;
    float inv = 1.0f / fmaxf(cntf[g], 1.0f);
    float s = 0.0f;
#pragma unroll
    for (int c = 0; c < HID; c++) s += pooled[g * 64 + c] * Wlin[c * 2 + o];
    out[g * 2 + o] = s * inv + blin[o];
}

// ---------------------------------------------------------------------------
extern "C" void kernel_launch(void* const* d_in, const int* in_sizes, int n_in,
                              void* d_out, int out_size) {
    const float* x    = (const float*)d_in[0];
    const int*   ei   = (const int*)d_in[1];
    const int*   batch= (const int*)d_in[2];
    const float* W1   = (const float*)d_in[3];
    const float* b1   = (const float*)d_in[4];
    const float* W2   = (const float*)d_in[5];
    const float* b2   = (const float*)d_in[6];
    const float* W3   = (const float*)d_in[7];
    const float* b3   = (const float*)d_in[8];
    const float* Wlin = (const float*)d_in[9];
    const float* blin = (const float*)d_in[10];
    float* out = (float*)d_out;

    const int n = in_sizes[2];
    const int E = in_sizes[1] / 2;

    __half* h16  = nullptr; cudaGetSymbolAddress((void**)&h16,  g_h16);
    float*  agg  = nullptr; cudaGetSymbolAddress((void**)&agg,  g_agg);
    float*  dinv = nullptr; cudaGetSymbolAddress((void**)&dinv, g_dinv);
    int*    cnt  = nullptr; cudaGetSymbolAddress((void**)&cnt,  g_cnt);
    int*    off  = nullptr; cudaGetSymbolAddress((void**)&off,  g_off);
    int*    cur  = nullptr; cudaGetSymbolAddress((void**)&cur,  g_cur);
    int*    bsum = nullptr; cudaGetSymbolAddress((void**)&bsum, g_bsum);
    int*    bbase= nullptr; cudaGetSymbolAddress((void**)&bbase,g_bbase);
    float2* csr  = nullptr; cudaGetSymbolAddress((void**)&csr,  g_csr);
    float*  pooled = nullptr; cudaGetSymbolAddress((void**)&pooled, g_pooled);
    float*  cntf = nullptr; cudaGetSymbolAddress((void**)&cntf, g_cntf);

    static cudaStream_t s2 = nullptr;
    static cudaEvent_t evFork = nullptr, evJoin = nullptr;
    if (!s2) {
        cudaStreamCreateWithFlags(&s2, cudaStreamNonBlocking);
        cudaEventCreateWithFlags(&evFork, cudaEventDisableTiming);
        cudaEventCreateWithFlags(&evJoin, cudaEventDisableTiming);
    }

    const int T = 256;
    const int nb = (n + 255) / 256;
    int gemmGrid   = (n + 127) / 128;
    int gatherGrid = (n * 16 + T - 1) / T;

    // fork: CSR build on s2, GEMM1 on default stream
    cudaEventRecord(evFork, 0);
    cudaStreamWaitEvent(s2, evFork, 0);

    cudaMemsetAsync(cnt, 0, (size_t)n * sizeof(int), s2);
    k_count<<<(E + T - 1) / T, T, 0, s2>>>(ei, E, cnt);
    k_scan_local<<<nb, 256, 0, s2>>>(cnt, n, off, bsum);
    k_scan_block<<<1, 512, 0, s2>>>(bsum, nb, bbase);
    k_scan_add<<<(n + T - 1) / T, T, 0, s2>>>(cnt, n, off, bbase, cur, dinv);
    k_fill<<<(E + T - 1) / T, T, 0, s2>>>(ei, E, dinv, cur, csr);
    cudaEventRecord(evJoin, s2);

    k_gemm<128, false><<<gemmGrid, T>>>(x, W1, h16, n);
    cudaMemsetAsync(pooled, 0, N_GRAPHS * HID * sizeof(float), 0);
    cudaMemsetAsync(cntf, 0, N_GRAPHS * sizeof(float), 0);

    cudaStreamWaitEvent(0, evJoin, 0);

    // layer 1
    k_gather<<<gatherGrid, T>>>(off, csr, dinv, h16, b1, agg, n);
    // layer 2
    k_gemm<64, true><<<gemmGrid, T>>>(agg, W2, h16, n);
    k_gather<<<gatherGrid, T>>>(off, csr, dinv, h16, b2, agg, n);
    // layer 3
    k_gemm<64, true><<<gemmGrid, T>>>(agg, W3, h16, n);
    k_gather<<<gatherGrid, T>>>(off, csr, dinv, h16, b3, agg, n);

    // pooling + head
    k_pool<<<(n + POOL_NODES - 1) / POOL_NODES, T>>>(agg, batch, n, pooled, cntf);
    k_final<<<1, 128>>>(pooled, cntf, Wlin, blin, out);
}

// round 11
// speedup vs baseline: 1.0350x; 1.0350x over previous
#include <cuda_runtime.h>
#include <cuda_fp16.h>
#include <cstdint>

#define MAX_NODES 100000
#define MAX_EDGES 1600000
#define HID 64
#define N_GRAPHS 64

// Scratch (no cudaMalloc allowed)
__device__ __half g_h16[MAX_NODES * HID];     // 12.8 MB
__device__ float  g_agg[MAX_NODES * HID];     // 25.6 MB
__device__ float  g_dinv[MAX_NODES];
__device__ int    g_cnt[MAX_NODES];
__device__ int    g_off[MAX_NODES + 1];
__device__ int    g_cur[MAX_NODES];
__device__ int    g_bsum[512];
__device__ int    g_bbase[512];
__device__ float2 g_csr[MAX_EDGES];           // {src_as_int_bits, coef}
__device__ float  g_pooled[N_GRAPHS * HID];
__device__ float  g_cntf[N_GRAPHS];

// ---------------------------------------------------------------------------
// CSR build
// ---------------------------------------------------------------------------
__global__ void k_count(const int* __restrict__ ei, int E, int* cnt) {
    int e = blockIdx.x * blockDim.x + threadIdx.x;
    if (e < E) atomicAdd(cnt + ei[E + e], 1);
}

__global__ void k_scan_local(const int* __restrict__ cnt, int n,
                             int* __restrict__ off, int* __restrict__ bsum) {
    __shared__ int s[256];
    int i = blockIdx.x * 256 + threadIdx.x;
    int v = (i < n) ? cnt[i] : 0;
    s[threadIdx.x] = v;
    __syncthreads();
    int val = v;
#pragma unroll
    for (int d = 1; d < 256; d <<= 1) {
        int t = (threadIdx.x >= d) ? s[threadIdx.x - d] : 0;
        __syncthreads();
        val += t;
        s[threadIdx.x] = val;
        __syncthreads();
    }
    if (i < n) off[i] = val - v;
    if (threadIdx.x == 255) bsum[blockIdx.x] = val;
}

__global__ void k_scan_block(int* __restrict__ bsum, int nb, int* __restrict__ bbase) {
    __shared__ int s[512];
    int t = threadIdx.x;
    int v = (t < nb) ? bsum[t] : 0;
    s[t] = v;
    __syncthreads();
    int val = v;
#pragma unroll
    for (int d = 1; d < 512; d <<= 1) {
        int x = (t >= d) ? s[t - d] : 0;
        __syncthreads();
        val += x;
        s[t] = val;
        __syncthreads();
    }
    if (t < nb) bbase[t] = val - v;
}

__global__ void k_scan_add(const int* __restrict__ cnt, int n,
                           int* __restrict__ off, const int* __restrict__ bbase,
                           int* __restrict__ cur, float* __restrict__ dinv) {
    int i = blockIdx.x * blockDim.x + threadIdx.x;
    if (i >= n) return;
    int o = off[i] + bbase[i >> 8];
    off[i] = o;
    cur[i] = o;
    dinv[i] = rsqrtf(1.0f + (float)cnt[i]);
    if (i == n - 1) off[n] = o + cnt[i];
}

__global__ void k_fill(const int* __restrict__ ei, int E,
                       const float* __restrict__ dinv,
                       int* __restrict__ cur, float2* __restrict__ csr) {
    int e = blockIdx.x * blockDim.x + threadIdx.x;
    if (e >= E) return;
    int r = ei[e];
    int c = ei[E + e];
    float coef = dinv[r] * dinv[c];
    int pos = atomicAdd(cur + c, 1);
    csr[pos] = make_float2(__int_as_float(r), coef);
}

// ---------------------------------------------------------------------------
// TF32 tensor-core GEMM: H16[n,64] = fp16( act(A[n,K]) @ W[K,64] )
// Block: 256 thr (8 warps), tile M=128 N=64, K-chunks of 32.
// Warp w computes rows [w*16, w*16+16) x all 64 cols via mma.m16n8k8.tf32.
// ---------------------------------------------------------------------------
__device__ __forceinline__ uint32_t f2tf32(float f) {
    uint32_t r;
    asm("cvt.rna.tf32.f32 %0, %1;" : "=r"(r) : "f"(f));
    return r;
}

template <int K, bool RELU>
__global__ void __launch_bounds__(256)
k_gemm(const float* __restrict__ A, const float* __restrict__ W,
       __half* __restrict__ H, int n) {
    __shared__ uint32_t As[128][36];   // bank = 4*gr + gc  (unique over warp)
    __shared__ uint32_t Ws[32][72];    // bank = 8*gc + gr  (unique over warp)

    const int t = threadIdx.x;
    const int warpId = t >> 5;
    const int lane = t & 31;
    const int gr = lane >> 2;          // 0..7
    const int gc = lane & 3;           // 0..3
    const int warpRow = warpId * 16;
    const int rowBase = blockIdx.x * 128;

    float acc[8][4];
#pragma unroll
    for (int j = 0; j < 8; j++)
#pragma unroll
        for (int i = 0; i < 4; i++) acc[j][i] = 0.0f;

#pragma unroll
    for (int kc = 0; kc < K; kc += 32) {
        // stage A chunk: 128 rows x 32 k  (4096 elems, 16/thread as 4 float4)
#pragma unroll
        for (int it = 0; it < 4; it++) {
            int idx = (it * 256 + t) * 4;
            int r = idx >> 5;
            int c = idx & 31;
            int grow = rowBase + r;
            float4 v = make_float4(0.f, 0.f, 0.f, 0.f);
            if (grow < n) {
                v = *reinterpret_cast<const float4*>(A + (long long)grow * K + kc + c);
                if (RELU) {
                    v.x = fmaxf(v.x, 0.f); v.y = fmaxf(v.y, 0.f);
                    v.z = fmaxf(v.z, 0.f); v.w = fmaxf(v.w, 0.f);
                }
            }
            As[r][c + 0] = f2tf32(v.x);
            As[r][c + 1] = f2tf32(v.y);
            As[r][c + 2] = f2tf32(v.z);
            As[r][c + 3] = f2tf32(v.w);
        }
        // stage W chunk: 32 k x 64 cols  (2048 elems, 8/thread as 2 float4)
#pragma unroll
        for (int it = 0; it < 2; it++) {
            int idx = (it * 256 + t) * 4;
            int k = idx >> 6;
            int c = idx & 63;
            float4 v = *reinterpret_cast<const float4*>(W + (long long)(kc + k) * 64 + c);
            Ws[k][c + 0] = f2tf32(v.x);
            Ws[k][c + 1] = f2tf32(v.y);
            Ws[k][c + 2] = f2tf32(v.z);
            Ws[k][c + 3] = f2tf32(v.w);
        }
        __syncthreads();

#pragma unroll
        for (int ks = 0; ks < 4; ks++) {
            int k0 = ks * 8;
            uint32_t a0 = As[warpRow + gr    ][k0 + gc];
            uint32_t a1 = As[warpRow + gr + 8][k0 + gc];
            uint32_t a2 = As[warpRow + gr    ][k0 + gc + 4];
            uint32_t a3 = As[warpRow + gr + 8][k0 + gc + 4];
#pragma unroll
            for (int j = 0; j < 8; j++) {
                uint32_t b0 = Ws[k0 + gc    ][j * 8 + gr];
                uint32_t b1 = Ws[k0 + gc + 4][j * 8 + gr];
                asm volatile(
                    "mma.sync.aligned.m16n8k8.row.col.f32.tf32.tf32.f32 "
                    "{%0,%1,%2,%3}, {%4,%5,%6,%7}, {%8,%9}, {%0,%1,%2,%3};"
                    : "+f"(acc[j][0]), "+f"(acc[j][1]), "+f"(acc[j][2]), "+f"(acc[j][3])
                    : "r"(a0), "r"(a1), "r"(a2), "r"(a3), "r"(b0), "r"(b1));
            }
        }
        __syncthreads();
    }

    // epilogue: fp16 store. c0,c1 are adjacent cols -> one __half2 per pair.
    int row0 = rowBase + warpRow + gr;
    int row1 = row0 + 8;
#pragma unroll
    for (int j = 0; j < 8; j++) {
        int col = j * 8 + gc * 2;
        if (row0 < n) {
            __half2 p = __floats2half2_rn(acc[j][0], acc[j][1]);
            *reinterpret_cast<__half2*>(H + (long long)row0 * 64 + col) = p;
        }
        if (row1 < n) {
            __half2 p = __floats2half2_rn(acc[j][2], acc[j][3]);
            *reinterpret_cast<__half2*>(H + (long long)row1 * 64 + col) = p;
        }
    }
}

// ---------------------------------------------------------------------------
// CSR gather (fp16 h): agg[node] = sum h16[src]*coef + h16[node]*dinv^2 + b
// ---------------------------------------------------------------------------
__device__ __forceinline__ void acc_h16(float4& acc, const __half* __restrict__ h,
                                        int r, int c4, float coef) {
    uint2 u = *reinterpret_cast<const uint2*>(h + (long long)r * 64 + c4 * 4);
    __half2 a = *reinterpret_cast<__half2*>(&u.x);
    __half2 b = *reinterpret_cast<__half2*>(&u.y);
    float2 f0 = __half22float2(a);
    float2 f1 = __half22float2(b);
    acc.x += f0.x * coef; acc.y += f0.y * coef;
    acc.z += f1.x * coef; acc.w += f1.y * coef;
}

__global__ void k_gather(const int* __restrict__ off, const float2* __restrict__ csr,
                         const float* __restrict__ dinv, const __half* __restrict__ h,
                         const float* __restrict__ b, float* __restrict__ agg, int n) {
    int gid = blockIdx.x * blockDim.x + threadIdx.x;
    int node = gid >> 4;
    int c4   = gid & 15;
    if (node >= n) return;

    float di = dinv[node];
    float4 bv = reinterpret_cast<const float4*>(b)[c4];
    float4 acc = bv;
    acc_h16(acc, h, node, c4, di * di);

    int k   = off[node];
    int end = off[node + 1];

    for (; k + 2 <= end; k += 2) {
        float2 d0 = csr[k];
        float2 d1 = csr[k + 1];
        int r0 = __float_as_int(d0.x);
        int r1 = __float_as_int(d1.x);
        uint2 u0 = *reinterpret_cast<const uint2*>(h + (long long)r0 * 64 + c4 * 4);
        uint2 u1 = *reinterpret_cast<const uint2*>(h + (long long)r1 * 64 + c4 * 4);
        __half2 a0 = *reinterpret_cast<__half2*>(&u0.x);
        __half2 b0 = *reinterpret_cast<__half2*>(&u0.y);
        __half2 a1 = *reinterpret_cast<__half2*>(&u1.x);
        __half2 b1 = *reinterpret_cast<__half2*>(&u1.y);
        float2 f00 = __half22float2(a0), f01 = __half22float2(b0);
        float2 f10 = __half22float2(a1), f11 = __half22float2(b1);
        acc.x += f00.x * d0.y; acc.y += f00.y * d0.y;
        acc.z += f01.x * d0.y; acc.w += f01.y * d0.y;
        acc.x += f10.x * d1.y; acc.y += f10.y * d1.y;
        acc.z += f11.x * d1.y; acc.w += f11.y * d1.y;
    }
    if (k < end) {
        float2 d = csr[k];
        acc_h16(acc, h, __float_as_int(d.x), c4, d.y);
    }
    reinterpret_cast<float4*>(agg)[node * 16 + c4] = acc;
}

// ---------------------------------------------------------------------------
// pooling + head
// ---------------------------------------------------------------------------
#define POOL_NODES 512
__global__ void k_pool(const float* __restrict__ agg, const int* __restrict__ batch,
                       int n, float* __restrict__ pooled, float* __restrict__ cntf) {
    __shared__ float acc[N_GRAPHS * HID];
    __shared__ float cs[N_GRAPHS];
    for (int i = threadIdx.x; i < N_GRAPHS * HID; i += blockDim.x) acc[i] = 0.f;
    if (threadIdx.x < N_GRAPHS) cs[threadIdx.x] = 0.f;
    __syncthreads();

    int base = blockIdx.x * POOL_NODES;
    int ch  = threadIdx.x & 63;
    int sub = threadIdx.x >> 6;
    for (int i = sub; i < POOL_NODES; i += 4) {
        int node = base + i;
        if (node >= n) break;
        int g = batch[node];
        float v = agg[(long long)node * 64 + ch];
        atomicAdd(&acc[g * 64 + ch], v);
        if (ch == 0) atomicAdd(&cs[g], 1.0f);
    }
    __syncthreads();

    for (int i = threadIdx.x; i < N_GRAPHS * HID; i += blockDim.x) {
        float v = acc[i];
        if (v != 0.f) atomicAdd(&pooled[i], v);
    }
    if (threadIdx.x < N_GRAPHS) {
        float v = cs[threadIdx.x];
        if (v != 0.f) atomicAdd(&cntf[threadIdx.x], v);
    }
}

__global__ void k_final(const float* __restrict__ pooled, const float* __restrict__ cntf,
                        const float* __restrict__ Wlin, const float* __restrict__ blin,
                        float* __restrict__ out) {
    int t = threadIdx.x;
    int g = t >> 1;
    int o = t & 1;
    float inv = 1.0f / fmaxf(cntf[g], 1.0f);
    float s = 0.0f;
#pragma unroll
    for (int c = 0; c < HID; c++) s += pooled[g * 64 + c] * Wlin[c * 2 + o];
    out[g * 2 + o] = s * inv + blin[o];
}

// ---------------------------------------------------------------------------
extern "C" void kernel_launch(void* const* d_in, const int* in_sizes, int n_in,
                              void* d_out, int out_size) {
    const float* x    = (const float*)d_in[0];
    const int*   ei   = (const int*)d_in[1];
    const int*   batch= (const int*)d_in[2];
    const float* W1   = (const float*)d_in[3];
    const float* b1   = (const float*)d_in[4];
    const float* W2   = (const float*)d_in[5];
    const float* b2   = (const float*)d_in[6];
    const float* W3   = (const float*)d_in[7];
    const float* b3   = (const float*)d_in[8];
    const float* Wlin = (const float*)d_in[9];
    const float* blin = (const float*)d_in[10];
    float* out = (float*)d_out;

    const int n = in_sizes[2];
    const int E = in_sizes[1] / 2;

    __half* h16  = nullptr; cudaGetSymbolAddress((void**)&h16,  g_h16);
    float*  agg  = nullptr; cudaGetSymbolAddress((void**)&agg,  g_agg);
    float*  dinv = nullptr; cudaGetSymbolAddress((void**)&dinv, g_dinv);
    int*    cnt  = nullptr; cudaGetSymbolAddress((void**)&cnt,  g_cnt);
    int*    off  = nullptr; cudaGetSymbolAddress((void**)&off,  g_off);
    int*    cur  = nullptr; cudaGetSymbolAddress((void**)&cur,  g_cur);
    int*    bsum = nullptr; cudaGetSymbolAddress((void**)&bsum, g_bsum);
    int*    bbase= nullptr; cudaGetSymbolAddress((void**)&bbase,g_bbase);
    float2* csr  = nullptr; cudaGetSymbolAddress((void**)&csr,  g_csr);
    float*  pooled = nullptr; cudaGetSymbolAddress((void**)&pooled, g_pooled);
    float*  cntf = nullptr; cudaGetSymbolAddress((void**)&cntf, g_cntf);

    static cudaStream_t s2 = nullptr;
    static cudaEvent_t evFork = nullptr, evJoin = nullptr;
    if (!s2) {
        cudaStreamCreateWithFlags(&s2, cudaStreamNonBlocking);
        cudaEventCreateWithFlags(&evFork, cudaEventDisableTiming);
        cudaEventCreateWithFlags(&evJoin, cudaEventDisableTiming);
    }

    const int T = 256;
    const int nb = (n + 255) / 256;
    int gemmGrid   = (n + 127) / 128;
    int gatherGrid = (n * 16 + T - 1) / T;

    // fork: CSR build on s2, GEMM1 on default stream
    cudaEventRecord(evFork, 0);
    cudaStreamWaitEvent(s2, evFork, 0);

    cudaMemsetAsync(cnt, 0, (size_t)n * sizeof(int), s2);
    k_count<<<(E + T - 1) / T, T, 0, s2>>>(ei, E, cnt);
    k_scan_local<<<nb, 256, 0, s2>>>(cnt, n, off, bsum);
    k_scan_block<<<1, 512, 0, s2>>>(bsum, nb, bbase);
    k_scan_add<<<(n + T - 1) / T, T, 0, s2>>>(cnt, n, off, bbase, cur, dinv);
    k_fill<<<(E + T - 1) / T, T, 0, s2>>>(ei, E, dinv, cur, csr);
    cudaEventRecord(evJoin, s2);

    k_gemm<128, false><<<gemmGrid, T>>>(x, W1, h16, n);
    cudaMemsetAsync(pooled, 0, N_GRAPHS * HID * sizeof(float), 0);
    cudaMemsetAsync(cntf, 0, N_GRAPHS * sizeof(float), 0);

    cudaStreamWaitEvent(0, evJoin, 0);

    // layer 1
    k_gather<<<gatherGrid, T>>>(off, csr, dinv, h16, b1, agg, n);
    // layer 2
    k_gemm<64, true><<<gemmGrid, T>>>(agg, W2, h16, n);
    k_gather<<<gatherGrid, T>>>(off, csr, dinv, h16, b2, agg, n);
    // layer 3
    k_gemm<64, true><<<gemmGrid, T>>>(agg, W3, h16, n);
    k_gather<<<gatherGrid, T>>>(off, csr, dinv, h16, b3, agg, n);

    // pooling + head
    k_pool<<<(n + POOL_NODES - 1) / POOL_NODES, T>>>(agg, batch, n, pooled, cntf);
    k_final<<<1, 128>>>(pooled, cntf, Wlin, blin, out);
}